// round 4
// baseline (speedup 1.0000x reference)
#include <cuda_runtime.h>

// Problem constants (fixed by the reference setup)
#define B_ROWS 32
#define NHITS  200
#define D0     6144
#define D1     350
#define OUT_N  5

// out[b, o] = bias[o] for all 32*5 outputs (d_out is poisoned to 0xAA).
__global__ void init_out_kernel(const float* __restrict__ bias,
                                float* __restrict__ out) {
    int i = threadIdx.x;
    if (i < B_ROWS * OUT_N) {
        out[i] = bias[i % OUT_N];
    }
}

// One block per row of the hit tensor x[32, 200, 3].
// Semantics of tensor_scatter_nd_update with ones: each UNIQUE (b, i0, i1)
// triple contributes W[i0*D1 + i1, :] exactly once to out[b, :].
__global__ void __launch_bounds__(224, 1)
scatter_gemv_kernel(const int* __restrict__ x,
                    const float* __restrict__ W,
                    float* __restrict__ out) {
    __shared__ int   sf[NHITS];           // flattened feature index per hit
    __shared__ int   sb[NHITS];           // batch value per hit (from data)
    __shared__ float acc[B_ROWS * OUT_N]; // per-(batch,out) accumulators

    const int t   = threadIdx.x;
    const int row = blockIdx.x;

    // zero accumulators
    for (int i = t; i < B_ROWS * OUT_N; i += blockDim.x) acc[i] = 0.0f;

    int f = -1, bv = -1;
    if (t < NHITS) {
        const int* h = x + ((long long)row * NHITS + t) * 3;
        bv = h[0];
        int i0 = h[1];
        int i1 = h[2];
        f = i0 * D1 + i1;
        sf[t] = f;
        sb[t] = bv;
    }
    __syncthreads();

    // Dedup: keep hit t only if no earlier hit k<t has the same (bv, f).
    // All threads iterate k over the full range reading the SAME shared
    // address per iteration -> broadcast, conflict-free.
    bool keep = (t < NHITS);
    #pragma unroll 4
    for (int k = 0; k < NHITS; k++) {
        int fk = sf[k];
        int bk = sb[k];
        if (k < t && fk == f && bk == bv) keep = false;
    }

    if (keep && bv >= 0 && bv < B_ROWS) {
        const float* w = W + (long long)f * OUT_N;
        float w0 = w[0], w1 = w[1], w2 = w[2], w3 = w[3], w4 = w[4];
        float* a = acc + bv * OUT_N;
        atomicAdd(&a[0], w0);
        atomicAdd(&a[1], w1);
        atomicAdd(&a[2], w2);
        atomicAdd(&a[3], w3);
        atomicAdd(&a[4], w4);
    }
    __syncthreads();

    // Flush nonzero accumulators to global output.
    for (int i = t; i < B_ROWS * OUT_N; i += blockDim.x) {
        float v = acc[i];
        if (v != 0.0f) atomicAdd(&out[i], v);
    }
}

extern "C" void kernel_launch(void* const* d_in, const int* in_sizes, int n_in,
                              void* d_out, int out_size) {
    // Identify inputs by element count (robust to metadata ordering):
    //   x    : 32*200*3 = 19200 int32
    //   W    : 2150400*5 = 10752000 float32 (largest)
    //   bias : 5 float32
    const int*   x    = nullptr;
    const float* W    = nullptr;
    const float* bias = nullptr;
    long long wmax = -1;
    for (int i = 0; i < n_in; i++) {
        long long sz = in_sizes[i];
        if (sz == B_ROWS * NHITS * 3) {
            x = (const int*)d_in[i];
        } else if (sz == OUT_N) {
            bias = (const float*)d_in[i];
        } else if (sz > wmax) {
            wmax = sz;
            W = (const float*)d_in[i];
        }
    }

    float* out = (float*)d_out;

    init_out_kernel<<<1, 256>>>(bias, out);
    scatter_gemv_kernel<<<B_ROWS, 224>>>(x, W, out);
}

// round 5
// speedup vs baseline: 4.0464x; 4.0464x over previous
#include <cuda_runtime.h>

// Problem constants (fixed by the reference setup)
#define B_ROWS 32
#define NHITS  200
#define D0     6144
#define D1     350
#define OUT_N  5
#define FULL_MASK 0xFFFFFFFFu

// out[b, o] = bias[o] for all 32*5 outputs (d_out is poisoned to 0xAA).
__global__ void init_out_kernel(const float* __restrict__ bias,
                                float* __restrict__ out) {
    int i = threadIdx.x;
    if (i < B_ROWS * OUT_N) {
        out[i] = bias[i % OUT_N];
    }
}

// One block per row of the hit tensor x[32, 200, 3].
// Semantics of tensor_scatter_nd_update with ones: each UNIQUE (b, i0, i1)
// triple contributes W[i0*D1 + i1, :] exactly once to out[b, :].
//
// Key perf fix vs previous version: NO same-address per-lane shared float
// atomics. Each warp butterfly-reduces its 5 partial sums and a single lane
// performs one shared atomicAdd per output. (All hits in a block share the
// same batch value in practice; a correctness fallback covers the general
// case without assuming it.)
__global__ void __launch_bounds__(256, 1)
scatter_gemv_kernel(const int* __restrict__ x,
                    const float* __restrict__ W,
                    float* __restrict__ out) {
    __shared__ int   skey[NHITS];          // packed (bv<<22)|f per hit
    __shared__ float acc[B_ROWS * OUT_N];  // per-(batch,out) accumulators

    const int t   = threadIdx.x;
    const int row = blockIdx.x;

    // zero accumulators
    for (int i = t; i < B_ROWS * OUT_N; i += blockDim.x) acc[i] = 0.0f;

    // f < D0*D1 = 2150400 < 2^22, bv < 32 -> key fits in 32 bits (27 used).
    int key = -1, f = -1, bv = -1;
    if (t < NHITS) {
        const int* h = x + (row * NHITS + t) * 3;
        bv = h[0];
        f  = h[1] * D1 + h[2];
        key = (bv << 22) | f;
        skey[t] = key;
    }
    __syncthreads();

    // Dedup: keep hit t only if no earlier hit k<t has the same key.
    // All threads read the SAME shared address per iteration -> broadcast.
    bool keep = (t < NHITS);
    #pragma unroll 8
    for (int k = 0; k < NHITS; k++) {
        int kk = skey[k];
        if (k < t && kk == key) keep = false;
    }

    // Gather the W row (5 floats); zero contribution if dropped/inactive.
    float c0 = 0.f, c1 = 0.f, c2 = 0.f, c3 = 0.f, c4 = 0.f;
    int bvl = -1;
    if (keep && bv >= 0 && bv < B_ROWS) {
        const float* w = W + (long long)f * OUT_N;
        c0 = __ldg(w + 0);
        c1 = __ldg(w + 1);
        c2 = __ldg(w + 2);
        c3 = __ldg(w + 3);
        c4 = __ldg(w + 4);
        bvl = bv;
    }

    // Max-reduce bv across the warp to find the (expected unique) batch value.
    int bmax = bvl;
    #pragma unroll
    for (int off = 16; off > 0; off >>= 1)
        bmax = max(bmax, __shfl_xor_sync(FULL_MASK, bmax, off));

    // Fast path: every contributing lane in this warp targets the same batch
    // row (true for the actual data). Butterfly-reduce, one atomic per output.
    bool uni = __all_sync(FULL_MASK, (bvl == -1) || (bvl == bmax));
    if (uni) {
        #pragma unroll
        for (int off = 16; off > 0; off >>= 1) {
            c0 += __shfl_xor_sync(FULL_MASK, c0, off);
            c1 += __shfl_xor_sync(FULL_MASK, c1, off);
            c2 += __shfl_xor_sync(FULL_MASK, c2, off);
            c3 += __shfl_xor_sync(FULL_MASK, c3, off);
            c4 += __shfl_xor_sync(FULL_MASK, c4, off);
        }
        if ((t & 31) == 0 && bmax >= 0) {
            float* a = acc + bmax * OUT_N;
            atomicAdd(&a[0], c0);
            atomicAdd(&a[1], c1);
            atomicAdd(&a[2], c2);
            atomicAdd(&a[3], c3);
            atomicAdd(&a[4], c4);
        }
    } else {
        // General-correctness fallback (mixed batch values within a warp);
        // never taken for the reference data.
        if (bvl >= 0) {
            float* a = acc + bvl * OUT_N;
            atomicAdd(&a[0], c0);
            atomicAdd(&a[1], c1);
            atomicAdd(&a[2], c2);
            atomicAdd(&a[3], c3);
            atomicAdd(&a[4], c4);
        }
    }
    __syncthreads();

    // Flush nonzero accumulators to global output (distinct rows per block in
    // practice -> negligible global atomic contention).
    for (int i = t; i < B_ROWS * OUT_N; i += blockDim.x) {
        float v = acc[i];
        if (v != 0.0f) atomicAdd(&out[i], v);
    }
}

extern "C" void kernel_launch(void* const* d_in, const int* in_sizes, int n_in,
                              void* d_out, int out_size) {
    // Identify inputs by element count (robust to metadata ordering):
    //   x    : 32*200*3 = 19200 int32
    //   W    : 2150400*5 = 10752000 float32 (largest)
    //   bias : 5 float32
    const int*   x    = nullptr;
    const float* W    = nullptr;
    const float* bias = nullptr;
    long long wmax = -1;
    for (int i = 0; i < n_in; i++) {
        long long sz = in_sizes[i];
        if (sz == B_ROWS * NHITS * 3) {
            x = (const int*)d_in[i];
        } else if (sz == OUT_N) {
            bias = (const float*)d_in[i];
        } else if (sz > wmax) {
            wmax = sz;
            W = (const float*)d_in[i];
        }
    }

    float* out = (float*)d_out;

    init_out_kernel<<<1, 256>>>(bias, out);
    scatter_gemv_kernel<<<B_ROWS, 256>>>(x, W, out);
}